// round 5
// baseline (speedup 1.0000x reference)
#include <cuda_runtime.h>
#include <math.h>
#include <cstdint>

#define NB 4
#define SS 2048
#define TD 768
#define HID 512
#define NH 8
#define HD 64
#define VD 768
#define MM (NB*SS)   // 8192

// Scratch
__device__ float g_Q[NB*NH*SS*HD];   // [bh][s][d]
__device__ float g_K[NB*NH*SS*HD];
__device__ float g_V[NB*NH*SS*HD];
__device__ float g_A[MM*HID];        // attended, [b*s][h*d]

// ---------------------------------------------------------------------------
// Helpers (all portable PTX valid on plain sm_103 target)
// ---------------------------------------------------------------------------
__device__ __forceinline__ uint32_t smem_u32(const void* p) {
    uint32_t a;
    asm("{ .reg .u64 t; cvta.to.shared.u64 t, %1; cvt.u32.u64 %0, t; }" : "=r"(a) : "l"(p));
    return a;
}
__device__ __forceinline__ float tf32r(float x) {
    uint32_t u;
    asm("cvt.rna.tf32.f32 %0, %1;" : "=r"(u) : "f"(x));
    return __uint_as_float(u);
}
__device__ __forceinline__ uint32_t cvt_tf32(uint32_t x) {
    uint32_t y;
    asm("cvt.rna.tf32.f32 %0, %1;" : "=r"(y) : "f"(__uint_as_float(x)));
    return y;
}
__device__ __forceinline__ void cp16(uint32_t dst, const void* src) {
    asm volatile("cp.async.ca.shared.global [%0], [%1], 16;" :: "r"(dst), "l"(src));
}
#define CP_COMMIT() asm volatile("cp.async.commit_group;" ::: "memory")
#define CP_WAIT(n)  asm volatile("cp.async.wait_group %0;" :: "n"(n) : "memory")

// ldmatrix.x4: 4x (8x8 b16) = 4x (8x4 tf32) tiles
__device__ __forceinline__ void ldsm4(uint32_t* r, uint32_t a) {
    asm volatile("ldmatrix.sync.aligned.m8n8.x4.shared.b16 {%0,%1,%2,%3}, [%4];"
        : "=r"(r[0]), "=r"(r[1]), "=r"(r[2]), "=r"(r[3]) : "r"(a));
}
// A-fragment address set (m16 x k8 tile at (m0, k0)), row-major [m][k], stride floats
__device__ __forceinline__ uint32_t a_addr(uint32_t base, int stride, int m0, int k0, int lane) {
    int sel = lane >> 3, r = lane & 7;
    return base + (((m0 + ((sel & 1) << 3) + r) * stride) + k0 + ((sel >> 1) << 2)) * 4;
}
// B-fragment address set: two n-octets (n0..n0+16) x k8 at k0, layout [n][k], stride floats
// -> regs {b0_octA, b1_octA, b0_octB, b1_octB}
__device__ __forceinline__ uint32_t b_addr(uint32_t base, int stride, int n0, int k0, int lane) {
    int sel = lane >> 3, r = lane & 7;
    return base + (((n0 + ((sel >> 1) << 3) + r) * stride) + k0 + ((sel & 1) << 2)) * 4;
}

// m16n8k8 tf32 MMA (g=lane>>2, tig=lane&3):
//  A: a0=[g][tig] a1=[g+8][tig] a2=[g][tig+4] a3=[g+8][tig+4]
//  B: b0=[k=tig][n=g] b1=[k=tig+4][n=g]
//  C: c0=[g][2tig] c1=[g][2tig+1] c2=[g+8][2tig] c3=[g+8][2tig+1]
__device__ __forceinline__ void mma8(float* c, const uint32_t* a, const uint32_t* b) {
    asm volatile(
        "mma.sync.aligned.m16n8k8.row.col.f32.tf32.tf32.f32 "
        "{%0,%1,%2,%3}, {%4,%5,%6,%7}, {%8,%9}, {%0,%1,%2,%3};"
        : "+f"(c[0]), "+f"(c[1]), "+f"(c[2]), "+f"(c[3])
        : "r"(a[0]), "r"(a[1]), "r"(a[2]), "r"(a[3]), "r"(b[0]), "r"(b[1]));
}

// ===========================================================================
// Projection GEMM body. CTA 128(M) x 64(N), BK=32, 128 threads (4 warps),
// warp tile 64x32. cp.async double-buffered; W transposed+rounded to [n][k].
// smem floats: X[2][128][36] | Wstag[2][32][64] | Wt[64][36]
// ===========================================================================
#define PX0 0
#define PX1 4608
#define PWS0 9216
#define PWS1 11264
#define PWT 13312
#define PROJ_SMEM (15616 * 4)

__device__ __forceinline__ void proj_issue(
    uint32_t sb, int buf, int kt,
    const float* __restrict__ A, int lda,
    const float* __restrict__ W, int ldw,
    int m0, int n0, int t)
{
    uint32_t xd = sb + (buf ? PX1 : PX0) * 4;
#pragma unroll
    for (int it = 0; it < 8; it++) {
        int i = t + it * 128;
        int r = i >> 3, fg = i & 7;
        cp16(xd + (r * 36 + fg * 4) * 4, &A[(size_t)(m0 + r) * lda + kt + fg * 4]);
    }
    uint32_t wd = sb + (buf ? PWS1 : PWS0) * 4;
#pragma unroll
    for (int it = 0; it < 4; it++) {
        int i = t + it * 128;
        int r = i >> 4, fg = i & 15;
        cp16(wd + (r * 64 + fg * 4) * 4, &W[(size_t)(kt + r) * ldw + n0 + fg * 4]);
    }
}

__device__ __forceinline__ void proj_body(
    float* sm, uint32_t sb,
    const float* __restrict__ A, int lda,
    const float* __restrict__ W, int ldw,
    int kdim, int m0, int n0, float acc[4][4][4])
{
    const int t = threadIdx.x;
    const int w = t >> 5, lane = t & 31;
    const int mw = (w >> 1) * 64, nw = (w & 1) * 32;

#pragma unroll
    for (int mi = 0; mi < 4; mi++)
#pragma unroll
        for (int nj = 0; nj < 4; nj++)
#pragma unroll
            for (int r = 0; r < 4; r++) acc[mi][nj][r] = 0.f;

    const int nc = kdim >> 5;
    proj_issue(sb, 0, 0, A, lda, W, ldw, m0, n0, t);
    CP_COMMIT();

    for (int c = 0; c < nc; c++) {
        if (c + 1 < nc) {
            proj_issue(sb, (c + 1) & 1, (c + 1) << 5, A, lda, W, ldw, m0, n0, t);
            CP_COMMIT();
            CP_WAIT(1);
        } else {
            CP_WAIT(0);
        }
        __syncthreads();

        // Transpose + round W staging -> Wt [64 n][36 k-pad]
        {
            const float* ws = sm + ((c & 1) ? PWS1 : PWS0);
#pragma unroll
            for (int it = 0; it < 4; it++) {
                int i = t + it * 128;
                int r = i >> 4, fg = i & 15;
                float4 v = *(const float4*)&ws[r * 64 + fg * 4];
                sm[PWT + (fg * 4 + 0) * 36 + r] = tf32r(v.x);
                sm[PWT + (fg * 4 + 1) * 36 + r] = tf32r(v.y);
                sm[PWT + (fg * 4 + 2) * 36 + r] = tf32r(v.z);
                sm[PWT + (fg * 4 + 3) * 36 + r] = tf32r(v.w);
            }
        }
        __syncthreads();

        uint32_t xb = sb + ((c & 1) ? PX1 : PX0) * 4;
        uint32_t wb = sb + PWT * 4;
#pragma unroll
        for (int ks = 0; ks < 4; ks++) {
            uint32_t af[4][4];
#pragma unroll
            for (int mi = 0; mi < 4; mi++) {
                ldsm4(af[mi], a_addr(xb, 36, mw + 16 * mi, ks * 8, lane));
#pragma unroll
                for (int j = 0; j < 4; j++) af[mi][j] = cvt_tf32(af[mi][j]);
            }
#pragma unroll
            for (int p = 0; p < 2; p++) {
                uint32_t bf[4];
                ldsm4(bf, b_addr(wb, 36, nw + p * 16, ks * 8, lane));
#pragma unroll
                for (int mi = 0; mi < 4; mi++) {
                    mma8(acc[mi][p * 2],     af[mi], bf);
                    mma8(acc[mi][p * 2 + 1], af[mi], bf + 2);
                }
            }
        }
        __syncthreads();
    }
}

// ---------------------------------------------------------------------------
// Kernel 1: fused QKV projection -> [bh][s][d]
// ---------------------------------------------------------------------------
__global__ __launch_bounds__(128) void qkv_mma(
    const float* __restrict__ X,
    const float* __restrict__ Wq, const float* __restrict__ bq,
    const float* __restrict__ Wk, const float* __restrict__ bk,
    const float* __restrict__ Wv, const float* __restrict__ bv)
{
    extern __shared__ float sm[];
    uint32_t sb = smem_u32(sm);

    const int z = blockIdx.z;
    const float* W    = (z == 0) ? Wq : (z == 1) ? Wk : Wv;
    const float* bias = (z == 0) ? bq : (z == 1) ? bk : bv;
    float* out        = (z == 0) ? g_Q : (z == 1) ? g_K : g_V;

    const int m0 = blockIdx.y * 128;
    const int n0 = blockIdx.x * 64;
    const int h  = blockIdx.x;

    float acc[4][4][4];
    proj_body(sm, sb, X, TD, W, HID, TD, m0, n0, acc);

    const int t = threadIdx.x;
    const int w = t >> 5, lane = t & 31, g = lane >> 2, tig = lane & 3;
    const int mw = (w >> 1) * 64, nw = (w & 1) * 32;

#pragma unroll
    for (int mi = 0; mi < 4; mi++) {
        int r = m0 + mw + 16 * mi + g;
        int b_ = r >> 11, s_ = r & 2047;
        float* base0 = out + ((((size_t)(b_ * NH + h)) * SS + s_) << 6);
        float* base1 = base0 + (8 << 6);
#pragma unroll
        for (int nj = 0; nj < 4; nj++) {
            int col = nw + nj * 8 + 2 * tig;
            float2 bb = *(const float2*)&bias[n0 + col];
            *(float2*)&base0[col] = make_float2(acc[mi][nj][0] + bb.x, acc[mi][nj][1] + bb.y);
            *(float2*)&base1[col] = make_float2(acc[mi][nj][2] + bb.x, acc[mi][nj][3] + bb.y);
        }
    }
}

// ---------------------------------------------------------------------------
// Kernel 3: output projection  out = g_A @ Wo + bo
// ---------------------------------------------------------------------------
__global__ __launch_bounds__(128) void oproj_mma(
    const float* __restrict__ Wo, const float* __restrict__ bo,
    float* __restrict__ out)
{
    extern __shared__ float sm[];
    uint32_t sb = smem_u32(sm);
    const int m0 = blockIdx.y * 128;
    const int n0 = blockIdx.x * 64;

    float acc[4][4][4];
    proj_body(sm, sb, g_A, HID, Wo, VD, HID, m0, n0, acc);

    const int t = threadIdx.x;
    const int w = t >> 5, lane = t & 31, g = lane >> 2, tig = lane & 3;
    const int mw = (w >> 1) * 64, nw = (w & 1) * 32;

#pragma unroll
    for (int mi = 0; mi < 4; mi++) {
        int r = m0 + mw + 16 * mi + g;
        float* base0 = out + (size_t)r * VD + n0;
        float* base1 = base0 + (size_t)8 * VD;
#pragma unroll
        for (int nj = 0; nj < 4; nj++) {
            int col = nw + nj * 8 + 2 * tig;
            float2 bb = *(const float2*)&bo[n0 + col];
            *(float2*)&base0[col] = make_float2(acc[mi][nj][0] + bb.x, acc[mi][nj][1] + bb.y);
            *(float2*)&base1[col] = make_float2(acc[mi][nj][2] + bb.x, acc[mi][nj][3] + bb.y);
        }
    }
}

// ===========================================================================
// Kernel 2: flash attention. 256 threads (8 warps), q-tile 128 (16 rows/warp),
// key tile 64, cp.async double-buffered K/V, ldmatrix fragments everywhere,
// V transposed+rounded to [d][s] per tile.
// smem floats: Q[128][68] | K[2][64][68] | Vstag[2][64][64] | Vt[64][68] | P[128][68]
// ===========================================================================
#define AQ   0
#define AK0  8704
#define AK1  13056
#define AVS0 17408
#define AVS1 21504
#define AVT  25600
#define AP   29952
#define ATTN_SMEM (38656 * 4)

__device__ __forceinline__ void attn_issue(
    uint32_t sb, int buf, const float* __restrict__ Kg,
    const float* __restrict__ Vg, int kt, int t)
{
    uint32_t kd = sb + (buf ? AK1 : AK0) * 4;
    uint32_t vd = sb + (buf ? AVS1 : AVS0) * 4;
    const float* Kt = Kg + (size_t)kt * 64 * 64;
    const float* Vt = Vg + (size_t)kt * 64 * 64;
#pragma unroll
    for (int it = 0; it < 4; it++) {
        int i = t + it * 256;
        int r = i >> 4, fg = i & 15;
        cp16(kd + (r * 68 + fg * 4) * 4, &Kt[r * 64 + fg * 4]);
        cp16(vd + (r * 64 + fg * 4) * 4, &Vt[r * 64 + fg * 4]);
    }
}

__global__ __launch_bounds__(256, 1) void attn_mma()
{
    extern __shared__ float sm[];
    uint32_t sb = smem_u32(sm);
    const int t = threadIdx.x;
    const int w = t >> 5, lane = t & 31, g = lane >> 2, tig = lane & 3;
    const int qt = blockIdx.x, bh = blockIdx.y;
    const int mrow = w * 16;

    const float* Qg = g_Q + (size_t)bh * SS * HD;
    const float* Kg = g_K + (size_t)bh * SS * HD;
    const float* Vg = g_V + (size_t)bh * SS * HD;

    // Prefetch K/V tile 0
    attn_issue(sb, 0, Kg, Vg, 0, t);
    CP_COMMIT();

    // Load Q tile [128][64], tf32-rounded
#pragma unroll
    for (int it = 0; it < 8; it++) {
        int i = t + it * 256;
        int r = i >> 4, fg = i & 15;
        float4 v = *(const float4*)&Qg[(size_t)(qt * 128 + r) * 64 + fg * 4];
        sm[AQ + r * 68 + fg * 4 + 0] = tf32r(v.x);
        sm[AQ + r * 68 + fg * 4 + 1] = tf32r(v.y);
        sm[AQ + r * 68 + fg * 4 + 2] = tf32r(v.z);
        sm[AQ + r * 68 + fg * 4 + 3] = tf32r(v.w);
    }
    __syncthreads();

    // Preload Q A-fragments (already tf32)
    uint32_t qa[8][4];
    {
        uint32_t qb = sb + AQ * 4;
#pragma unroll
        for (int ks = 0; ks < 8; ks++)
            ldsm4(qa[ks], a_addr(qb, 68, mrow, ks * 8, lane));
    }

    float o[8][4];
#pragma unroll
    for (int nj = 0; nj < 8; nj++)
#pragma unroll
        for (int r = 0; r < 4; r++) o[nj][r] = 0.f;
    float m0 = -1e30f, m1 = -1e30f, l0 = 0.f, l1 = 0.f;

    for (int kt = 0; kt < 32; kt++) {
        if (kt + 1 < 32) {
            attn_issue(sb, (kt + 1) & 1, Kg, Vg, kt + 1, t);
            CP_COMMIT();
            CP_WAIT(1);
        } else {
            CP_WAIT(0);
        }
        __syncthreads();   // tile kt ready; prev iter's Vt/P reads complete

        // Transpose + round V -> Vt [64 d][68]
        {
            const float* vs = sm + ((kt & 1) ? AVS1 : AVS0);
#pragma unroll
            for (int it = 0; it < 4; it++) {
                int i = t + it * 256;
                int r = i >> 4, fg = i & 15;
                float4 v = *(const float4*)&vs[r * 64 + fg * 4];
                sm[AVT + (fg * 4 + 0) * 68 + r] = tf32r(v.x);
                sm[AVT + (fg * 4 + 1) * 68 + r] = tf32r(v.y);
                sm[AVT + (fg * 4 + 2) * 68 + r] = tf32r(v.z);
                sm[AVT + (fg * 4 + 3) * 68 + r] = tf32r(v.w);
            }
        }
        __syncthreads();

        // S = Q K^T
        float s[8][4];
#pragma unroll
        for (int nj = 0; nj < 8; nj++)
#pragma unroll
            for (int r = 0; r < 4; r++) s[nj][r] = 0.f;

        uint32_t kb = sb + ((kt & 1) ? AK1 : AK0) * 4;
#pragma unroll
        for (int ks = 0; ks < 8; ks++)
#pragma unroll
            for (int p = 0; p < 4; p++) {
                uint32_t bf[4];
                ldsm4(bf, b_addr(kb, 68, p * 16, ks * 8, lane));
                bf[0] = cvt_tf32(bf[0]); bf[1] = cvt_tf32(bf[1]);
                bf[2] = cvt_tf32(bf[2]); bf[3] = cvt_tf32(bf[3]);
                mma8(s[p * 2],     qa[ks], bf);
                mma8(s[p * 2 + 1], qa[ks], bf + 2);
            }

        // Online softmax in registers
        float mx0 = m0, mx1 = m1;
#pragma unroll
        for (int nj = 0; nj < 8; nj++) {
            s[nj][0] *= 0.125f; s[nj][1] *= 0.125f;
            s[nj][2] *= 0.125f; s[nj][3] *= 0.125f;
            mx0 = fmaxf(mx0, fmaxf(s[nj][0], s[nj][1]));
            mx1 = fmaxf(mx1, fmaxf(s[nj][2], s[nj][3]));
        }
        mx0 = fmaxf(mx0, __shfl_xor_sync(0xffffffffu, mx0, 1));
        mx0 = fmaxf(mx0, __shfl_xor_sync(0xffffffffu, mx0, 2));
        mx1 = fmaxf(mx1, __shfl_xor_sync(0xffffffffu, mx1, 1));
        mx1 = fmaxf(mx1, __shfl_xor_sync(0xffffffffu, mx1, 2));

        float corr0 = __expf(m0 - mx0), corr1 = __expf(m1 - mx1);
        float ls0 = 0.f, ls1 = 0.f;
#pragma unroll
        for (int nj = 0; nj < 8; nj++) {
            float p0 = __expf(s[nj][0] - mx0);
            float p1 = __expf(s[nj][1] - mx0);
            float p2 = __expf(s[nj][2] - mx1);
            float p3 = __expf(s[nj][3] - mx1);
            ls0 += p0 + p1;
            ls1 += p2 + p3;
            *(float2*)&sm[AP + (mrow + g) * 68 + nj * 8 + 2 * tig] =
                make_float2(tf32r(p0), tf32r(p1));
            *(float2*)&sm[AP + (mrow + g + 8) * 68 + nj * 8 + 2 * tig] =
                make_float2(tf32r(p2), tf32r(p3));
        }
        ls0 += __shfl_xor_sync(0xffffffffu, ls0, 1);
        ls0 += __shfl_xor_sync(0xffffffffu, ls0, 2);
        ls1 += __shfl_xor_sync(0xffffffffu, ls1, 1);
        ls1 += __shfl_xor_sync(0xffffffffu, ls1, 2);
        l0 = l0 * corr0 + ls0;
        l1 = l1 * corr1 + ls1;
        m0 = mx0; m1 = mx1;

#pragma unroll
        for (int nj = 0; nj < 8; nj++) {
            o[nj][0] *= corr0; o[nj][1] *= corr0;
            o[nj][2] *= corr1; o[nj][3] *= corr1;
        }
        __syncwarp();   // P rows are warp-private

        // O += P V   (P and Vt already tf32)
        uint32_t pb = sb + AP * 4;
        uint32_t vb = sb + AVT * 4;
#pragma unroll
        for (int ks = 0; ks < 8; ks++) {
            uint32_t pa[4];
            ldsm4(pa, a_addr(pb, 68, mrow, ks * 8, lane));
#pragma unroll
            for (int p = 0; p < 4; p++) {
                uint32_t bf[4];
                ldsm4(bf, b_addr(vb, 68, p * 16, ks * 8, lane));
                mma8(o[p * 2],     pa, bf);
                mma8(o[p * 2 + 1], pa, bf + 2);
            }
        }
    }

    // Epilogue: normalize, write g_A [b*s][h*64]
    const float inv0 = 1.f / l0, inv1 = 1.f / l1;
    const int b_ = bh >> 3, h = bh & 7;
    const int r0 = qt * 128 + mrow + g;
    float* p0 = g_A + ((size_t)(b_ * SS + r0)) * HID + h * 64;
    float* p1 = p0 + (size_t)8 * HID;
#pragma unroll
    for (int nj = 0; nj < 8; nj++) {
        *(float2*)&p0[nj * 8 + 2 * tig] = make_float2(o[nj][0] * inv0, o[nj][1] * inv0);
        *(float2*)&p1[nj * 8 + 2 * tig] = make_float2(o[nj][2] * inv1, o[nj][3] * inv1);
    }
}

// ===========================================================================
extern "C" void kernel_launch(void* const* d_in, const int* in_sizes, int n_in,
                              void* d_out, int out_size)
{
    const float* X  = (const float*)d_in[0];
    const float* Wq = (const float*)d_in[1];
    const float* bq = (const float*)d_in[2];
    const float* Wk = (const float*)d_in[3];
    const float* bk = (const float*)d_in[4];
    const float* Wv = (const float*)d_in[5];
    const float* bv = (const float*)d_in[6];
    const float* Wo = (const float*)d_in[7];
    const float* bo = (const float*)d_in[8];
    float* out = (float*)d_out;

    cudaFuncSetAttribute(qkv_mma,   cudaFuncAttributeMaxDynamicSharedMemorySize, PROJ_SMEM);
    cudaFuncSetAttribute(oproj_mma, cudaFuncAttributeMaxDynamicSharedMemorySize, PROJ_SMEM);
    cudaFuncSetAttribute(attn_mma,  cudaFuncAttributeMaxDynamicSharedMemorySize, ATTN_SMEM);

    qkv_mma<<<dim3(HID / 64, MM / 128, 3), 128, PROJ_SMEM>>>(X, Wq, bq, Wk, bk, Wv, bv);
    attn_mma<<<dim3(SS / 128, NB * NH), 256, ATTN_SMEM>>>();
    oproj_mma<<<dim3(VD / 64, MM / 128), 128, PROJ_SMEM>>>(Wo, bo, out);
}

// round 6
// speedup vs baseline: 1.3514x; 1.3514x over previous
#include <cuda_runtime.h>
#include <math.h>
#include <cstdint>

#define NB 4
#define SS 2048
#define TD 768
#define HID 512
#define NH 8
#define HD 64
#define VD 768
#define MM (NB*SS)   // 8192

// Scratch
__device__ float g_Q[NB*NH*SS*HD];   // [bh][s][d]
__device__ float g_K[NB*NH*SS*HD];
__device__ float g_V[NB*NH*SS*HD];
__device__ float g_A[MM*HID];        // attended, [b*s][h*d]

// ---------------------------------------------------------------------------
// Helpers (portable PTX, valid on plain sm_103 target)
// ---------------------------------------------------------------------------
__device__ __forceinline__ uint32_t smem_u32(const void* p) {
    uint32_t a;
    asm("{ .reg .u64 t; cvta.to.shared.u64 t, %1; cvt.u32.u64 %0, t; }" : "=r"(a) : "l"(p));
    return a;
}
__device__ __forceinline__ float tf32r(float x) {
    uint32_t u;
    asm("cvt.rna.tf32.f32 %0, %1;" : "=r"(u) : "f"(x));
    return __uint_as_float(u);
}
__device__ __forceinline__ uint32_t cvtb(float x) {
    uint32_t y;
    asm("cvt.rna.tf32.f32 %0, %1;" : "=r"(y) : "f"(x));
    return y;
}
__device__ __forceinline__ void cp16(uint32_t dst, const void* src) {
    asm volatile("cp.async.ca.shared.global [%0], [%1], 16;" :: "r"(dst), "l"(src));
}
#define CP_COMMIT() asm volatile("cp.async.commit_group;" ::: "memory")
#define CP_WAIT0()  asm volatile("cp.async.wait_group 0;" ::: "memory")

// ldmatrix.x4 (tf32 trick: 8x4 tf32 tile == 8x8 b16 tile)
__device__ __forceinline__ void ldsm4(uint32_t* r, uint32_t a) {
    asm volatile("ldmatrix.sync.aligned.m8n8.x4.shared.b16 {%0,%1,%2,%3}, [%4];"
        : "=r"(r[0]), "=r"(r[1]), "=r"(r[2]), "=r"(r[3]) : "r"(a));
}
// A-fragment addresses: m16 x k8 tile at (m0,k0) in row-major [m][k], stride floats
__device__ __forceinline__ uint32_t a_addr(uint32_t base, int stride, int m0, int k0, int lane) {
    int sel = lane >> 3, r = lane & 7;
    return base + (((m0 + ((sel & 1) << 3) + r) * stride) + k0 + ((sel >> 1) << 2)) * 4;
}
// B-fragment addresses: two n-octets at (n0, k0) in [n][k] layout -> {b0,b1,b0',b1'}
__device__ __forceinline__ uint32_t b_addr(uint32_t base, int stride, int n0, int k0, int lane) {
    int sel = lane >> 3, r = lane & 7;
    return base + (((n0 + ((sel >> 1) << 3) + r) * stride) + k0 + ((sel & 1) << 2)) * 4;
}

// m16n8k8 tf32 MMA (g=lane>>2, tig=lane&3):
//  A: a0=[g][tig] a1=[g+8][tig] a2=[g][tig+4] a3=[g+8][tig+4]
//  B: b0=[k=tig][n=g] b1=[k=tig+4][n=g]
//  C: c0=[g][2tig] c1=[g][2tig+1] c2=[g+8][2tig] c3=[g+8][2tig+1]
__device__ __forceinline__ void mma8(float* c, const uint32_t* a, const uint32_t* b) {
    asm volatile(
        "mma.sync.aligned.m16n8k8.row.col.f32.tf32.tf32.f32 "
        "{%0,%1,%2,%3}, {%4,%5,%6,%7}, {%8,%9}, {%0,%1,%2,%3};"
        : "+f"(c[0]), "+f"(c[1]), "+f"(c[2]), "+f"(c[3])
        : "r"(a[0]), "r"(a[1]), "r"(a[2]), "r"(a[3]), "r"(b[0]), "r"(b[1]));
}

// ===========================================================================
// Projection GEMM body. CTA 128(M) x 64(N), BK=32, 128 threads (4 warps),
// warp tile 64x32. cp.async double-buffered, NO transposes:
//   A-frags: ldmatrix from X [m][k] (stride 36, conflict-free)
//   B-frags: scalar LDS from W [k][n] (stride 72, banks 8*tig+g, conflict-free)
// tf32 RNA rounding applied in registers after fragment load.
// smem floats: X[2][128][36] | W[2][32][72]
// ===========================================================================
#define PX0 0
#define PX1 4608
#define PW0 9216
#define PW1 11520
#define PROJ_SMEM (13824 * 4)

__device__ __forceinline__ void proj_issue(
    uint32_t sb, int buf, int kt,
    const float* __restrict__ A, int lda,
    const float* __restrict__ W, int ldw,
    int m0, int n0, int t)
{
    uint32_t xd = sb + (buf ? PX1 : PX0) * 4;
#pragma unroll
    for (int it = 0; it < 8; it++) {
        int i = t + it * 128;
        int r = i >> 3, fg = i & 7;
        cp16(xd + (r * 36 + fg * 4) * 4, &A[(size_t)(m0 + r) * lda + kt + fg * 4]);
    }
    uint32_t wd = sb + (buf ? PW1 : PW0) * 4;
#pragma unroll
    for (int it = 0; it < 4; it++) {
        int i = t + it * 128;
        int r = i >> 4, fg = i & 15;
        cp16(wd + (r * 72 + fg * 4) * 4, &W[(size_t)(kt + r) * ldw + n0 + fg * 4]);
    }
}

__device__ __forceinline__ void proj_body(
    float* sm, uint32_t sb,
    const float* __restrict__ A, int lda,
    const float* __restrict__ W, int ldw,
    int kdim, int m0, int n0, float acc[4][4][4])
{
    const int t = threadIdx.x;
    const int w = t >> 5, lane = t & 31, g = lane >> 2, tig = lane & 3;
    const int mw = (w >> 1) * 64, nw = (w & 1) * 32;

#pragma unroll
    for (int mi = 0; mi < 4; mi++)
#pragma unroll
        for (int nj = 0; nj < 4; nj++)
#pragma unroll
            for (int r = 0; r < 4; r++) acc[mi][nj][r] = 0.f;

    const int nc = kdim >> 5;
    proj_issue(sb, 0, 0, A, lda, W, ldw, m0, n0, t);
    CP_COMMIT();

    for (int c = 0; c < nc; c++) {
        CP_WAIT0();
        __syncthreads();   // chunk c visible; chunk c-1 consumption finished
        if (c + 1 < nc) {
            proj_issue(sb, (c + 1) & 1, (c + 1) << 5, A, lda, W, ldw, m0, n0, t);
            CP_COMMIT();
        }
        uint32_t xb = sb + ((c & 1) ? PX1 : PX0) * 4;
        const float* ws = sm + ((c & 1) ? PW1 : PW0);

#pragma unroll
        for (int ks = 0; ks < 4; ks++) {
            uint32_t af[4][4];
#pragma unroll
            for (int mi = 0; mi < 4; mi++) {
                ldsm4(af[mi], a_addr(xb, 36, mw + 16 * mi, ks * 8, lane));
#pragma unroll
                for (int j = 0; j < 4; j++) af[mi][j] = cvtb(__uint_as_float(af[mi][j]));
            }
#pragma unroll
            for (int nj = 0; nj < 4; nj++) {
                uint32_t bf[2];
                bf[0] = cvtb(ws[(ks * 8 + tig) * 72 + nw + nj * 8 + g]);
                bf[1] = cvtb(ws[(ks * 8 + tig + 4) * 72 + nw + nj * 8 + g]);
#pragma unroll
                for (int mi = 0; mi < 4; mi++)
                    mma8(acc[mi][nj], af[mi], bf);
            }
        }
    }
}

// ---------------------------------------------------------------------------
// Kernel 1: fused QKV projection -> [bh][s][d]
// ---------------------------------------------------------------------------
__global__ __launch_bounds__(128) void qkv_mma(
    const float* __restrict__ X,
    const float* __restrict__ Wq, const float* __restrict__ bq,
    const float* __restrict__ Wk, const float* __restrict__ bk,
    const float* __restrict__ Wv, const float* __restrict__ bv)
{
    extern __shared__ float sm[];
    uint32_t sb = smem_u32(sm);

    const int z = blockIdx.z;
    const float* W    = (z == 0) ? Wq : (z == 1) ? Wk : Wv;
    const float* bias = (z == 0) ? bq : (z == 1) ? bk : bv;
    float* out        = (z == 0) ? g_Q : (z == 1) ? g_K : g_V;

    const int m0 = blockIdx.y * 128;
    const int n0 = blockIdx.x * 64;
    const int h  = blockIdx.x;

    float acc[4][4][4];
    proj_body(sm, sb, X, TD, W, HID, TD, m0, n0, acc);

    const int t = threadIdx.x;
    const int w = t >> 5, lane = t & 31, g = lane >> 2, tig = lane & 3;
    const int mw = (w >> 1) * 64, nw = (w & 1) * 32;

#pragma unroll
    for (int mi = 0; mi < 4; mi++) {
        int r = m0 + mw + 16 * mi + g;
        int b_ = r >> 11, s_ = r & 2047;
        float* base0 = out + ((((size_t)(b_ * NH + h)) * SS + s_) << 6);
        float* base1 = base0 + (8 << 6);
#pragma unroll
        for (int nj = 0; nj < 4; nj++) {
            int col = nw + nj * 8 + 2 * tig;
            float2 bb = *(const float2*)&bias[n0 + col];
            *(float2*)&base0[col] = make_float2(acc[mi][nj][0] + bb.x, acc[mi][nj][1] + bb.y);
            *(float2*)&base1[col] = make_float2(acc[mi][nj][2] + bb.x, acc[mi][nj][3] + bb.y);
        }
    }
}

// ---------------------------------------------------------------------------
// Kernel 3: output projection  out = g_A @ Wo + bo
// ---------------------------------------------------------------------------
__global__ __launch_bounds__(128) void oproj_mma(
    const float* __restrict__ Wo, const float* __restrict__ bo,
    float* __restrict__ out)
{
    extern __shared__ float sm[];
    uint32_t sb = smem_u32(sm);
    const int m0 = blockIdx.y * 128;
    const int n0 = blockIdx.x * 64;

    float acc[4][4][4];
    proj_body(sm, sb, g_A, HID, Wo, VD, HID, m0, n0, acc);

    const int t = threadIdx.x;
    const int w = t >> 5, lane = t & 31, g = lane >> 2, tig = lane & 3;
    const int mw = (w >> 1) * 64, nw = (w & 1) * 32;

#pragma unroll
    for (int mi = 0; mi < 4; mi++) {
        int r = m0 + mw + 16 * mi + g;
        float* base0 = out + (size_t)r * VD + n0;
        float* base1 = base0 + (size_t)8 * VD;
#pragma unroll
        for (int nj = 0; nj < 4; nj++) {
            int col = nw + nj * 8 + 2 * tig;
            float2 bb = *(const float2*)&bo[n0 + col];
            *(float2*)&base0[col] = make_float2(acc[mi][nj][0] + bb.x, acc[mi][nj][1] + bb.y);
            *(float2*)&base1[col] = make_float2(acc[mi][nj][2] + bb.x, acc[mi][nj][3] + bb.y);
        }
    }
}

// ===========================================================================
// Kernel 2: flash attention. 128 threads (4 warps), q-tile 128 -> 32 rows
// per warp (2 m-tiles: B-fragment reuse x2). Key tile 32, cp.async
// double-buffered K/V. K consumed via ldmatrix ([n][k] natural layout),
// V via scalar B-LDS ([k][n] natural layout) — no transposes.
// smem floats: Q[128][68] | K[2][32][68] | V[2][32][72] | P[128][36]
// ===========================================================================
#define AQ  0
#define AK0 8704
#define AK1 10880
#define AV0 13056
#define AV1 15360
#define AP  17664
#define ATTN_SMEM (22272 * 4)
#define NIT (SS / 32)   // 64 key tiles

__device__ __forceinline__ void attn_issue(
    uint32_t sb, int buf, const float* __restrict__ Kg,
    const float* __restrict__ Vg, int kt, int t)
{
    uint32_t kd = sb + (buf ? AK1 : AK0) * 4;
    uint32_t vd = sb + (buf ? AV1 : AV0) * 4;
    const float* Kt = Kg + (size_t)kt * 32 * 64;
    const float* Vt = Vg + (size_t)kt * 32 * 64;
#pragma unroll
    for (int it = 0; it < 4; it++) {
        int i = t + it * 128;
        int r = i >> 4, fg = i & 15;
        cp16(kd + (r * 68 + fg * 4) * 4, &Kt[r * 64 + fg * 4]);
        cp16(vd + (r * 72 + fg * 4) * 4, &Vt[r * 64 + fg * 4]);
    }
}

__global__ __launch_bounds__(128, 1) void attn_mma()
{
    extern __shared__ float sm[];
    uint32_t sb = smem_u32(sm);
    const int t = threadIdx.x;
    const int w = t >> 5, lane = t & 31, g = lane >> 2, tig = lane & 3;
    const int qt = blockIdx.x, bh = blockIdx.y;
    const int mrow = w * 32;

    const float* Qg = g_Q + (size_t)bh * SS * HD;
    const float* Kg = g_K + (size_t)bh * SS * HD;
    const float* Vg = g_V + (size_t)bh * SS * HD;

    attn_issue(sb, 0, Kg, Vg, 0, t);
    CP_COMMIT();

    // Load Q tile [128][64], tf32-rounded once
#pragma unroll
    for (int it = 0; it < 16; it++) {
        int i = t + it * 128;
        int r = i >> 4, fg = i & 15;
        float4 v = *(const float4*)&Qg[(size_t)(qt * 128 + r) * 64 + fg * 4];
        v.x = tf32r(v.x); v.y = tf32r(v.y); v.z = tf32r(v.z); v.w = tf32r(v.w);
        *(float4*)&sm[AQ + r * 68 + fg * 4] = v;
    }

    float o[2][8][4];
#pragma unroll
    for (int mt = 0; mt < 2; mt++)
#pragma unroll
        for (int nj = 0; nj < 8; nj++)
#pragma unroll
            for (int r = 0; r < 4; r++) o[mt][nj][r] = 0.f;
    float mr[2][2] = {{-1e30f, -1e30f}, {-1e30f, -1e30f}};
    float lr[2][2] = {{0.f, 0.f}, {0.f, 0.f}};

    for (int kt = 0; kt < NIT; kt++) {
        CP_WAIT0();
        __syncthreads();   // tile kt visible; tile kt-1 consumption done
        if (kt + 1 < NIT) {
            attn_issue(sb, (kt + 1) & 1, Kg, Vg, kt + 1, t);
            CP_COMMIT();
        }
        uint32_t kb = sb + ((kt & 1) ? AK1 : AK0) * 4;

        // S = Q K^T  (32 rows x 32 keys per warp)
        float s[2][4][4];
#pragma unroll
        for (int mt = 0; mt < 2; mt++)
#pragma unroll
            for (int nj = 0; nj < 4; nj++)
#pragma unroll
                for (int r = 0; r < 4; r++) s[mt][nj][r] = 0.f;

#pragma unroll
        for (int ks = 0; ks < 8; ks++) {
            uint32_t qa0[4], qa1[4];
            ldsm4(qa0, a_addr(sb, 68, mrow, ks * 8, lane));
            ldsm4(qa1, a_addr(sb, 68, mrow + 16, ks * 8, lane));
#pragma unroll
            for (int p = 0; p < 2; p++) {
                uint32_t bf[4];
                ldsm4(bf, b_addr(kb, 68, p * 16, ks * 8, lane));
                bf[0] = cvtb(__uint_as_float(bf[0])); bf[1] = cvtb(__uint_as_float(bf[1]));
                bf[2] = cvtb(__uint_as_float(bf[2])); bf[3] = cvtb(__uint_as_float(bf[3]));
                mma8(s[0][p * 2],     qa0, bf);
                mma8(s[0][p * 2 + 1], qa0, bf + 2);
                mma8(s[1][p * 2],     qa1, bf);
                mma8(s[1][p * 2 + 1], qa1, bf + 2);
            }
        }

        // Online softmax: 4 row-groups (mt x {g, g+8}), quad reduction
        float corr[2][2];
#pragma unroll
        for (int mt = 0; mt < 2; mt++) {
            float mx0 = mr[mt][0], mx1 = mr[mt][1];
#pragma unroll
            for (int nj = 0; nj < 4; nj++) {
                s[mt][nj][0] *= 0.125f; s[mt][nj][1] *= 0.125f;
                s[mt][nj][2] *= 0.125f; s[mt][nj][3] *= 0.125f;
                mx0 = fmaxf(mx0, fmaxf(s[mt][nj][0], s[mt][nj][1]));
                mx1 = fmaxf(mx1, fmaxf(s[mt][nj][2], s[mt][nj][3]));
            }
            mx0 = fmaxf(mx0, __shfl_xor_sync(0xffffffffu, mx0, 1));
            mx0 = fmaxf(mx0, __shfl_xor_sync(0xffffffffu, mx0, 2));
            mx1 = fmaxf(mx1, __shfl_xor_sync(0xffffffffu, mx1, 1));
            mx1 = fmaxf(mx1, __shfl_xor_sync(0xffffffffu, mx1, 2));

            corr[mt][0] = __expf(mr[mt][0] - mx0);
            corr[mt][1] = __expf(mr[mt][1] - mx1);
            float ls0 = 0.f, ls1 = 0.f;
            int row0 = mrow + 16 * mt + g;
#pragma unroll
            for (int nj = 0; nj < 4; nj++) {
                float p0 = __expf(s[mt][nj][0] - mx0);
                float p1 = __expf(s[mt][nj][1] - mx0);
                float p2 = __expf(s[mt][nj][2] - mx1);
                float p3 = __expf(s[mt][nj][3] - mx1);
                ls0 += p0 + p1;
                ls1 += p2 + p3;
                *(float2*)&sm[AP + row0 * 36 + nj * 8 + 2 * tig] =
                    make_float2(tf32r(p0), tf32r(p1));
                *(float2*)&sm[AP + (row0 + 8) * 36 + nj * 8 + 2 * tig] =
                    make_float2(tf32r(p2), tf32r(p3));
            }
            ls0 += __shfl_xor_sync(0xffffffffu, ls0, 1);
            ls0 += __shfl_xor_sync(0xffffffffu, ls0, 2);
            ls1 += __shfl_xor_sync(0xffffffffu, ls1, 1);
            ls1 += __shfl_xor_sync(0xffffffffu, ls1, 2);
            lr[mt][0] = lr[mt][0] * corr[mt][0] + ls0;
            lr[mt][1] = lr[mt][1] * corr[mt][1] + ls1;
            mr[mt][0] = mx0; mr[mt][1] = mx1;

#pragma unroll
            for (int nj = 0; nj < 8; nj++) {
                o[mt][nj][0] *= corr[mt][0]; o[mt][nj][1] *= corr[mt][0];
                o[mt][nj][2] *= corr[mt][1]; o[mt][nj][3] *= corr[mt][1];
            }
        }
        __syncwarp();   // P rows are warp-private (warp owns rows mrow..mrow+31)

        // O += P V   (keys = 4 k-steps of 8; V [k][n] scalar B-frags)
        uint32_t pb = sb + AP * 4;
        const float* vs = sm + ((kt & 1) ? AV1 : AV0);
#pragma unroll
        for (int ks = 0; ks < 4; ks++) {
            uint32_t pa0[4], pa1[4];
            ldsm4(pa0, a_addr(pb, 36, mrow, ks * 8, lane));
            ldsm4(pa1, a_addr(pb, 36, mrow + 16, ks * 8, lane));
#pragma unroll
            for (int nj = 0; nj < 8; nj++) {
                uint32_t bf[2];
                bf[0] = cvtb(vs[(ks * 8 + tig) * 72 + nj * 8 + g]);
                bf[1] = cvtb(vs[(ks * 8 + tig + 4) * 72 + nj * 8 + g]);
                mma8(o[0][nj], pa0, bf);
                mma8(o[1][nj], pa1, bf);
            }
        }
    }

    // Epilogue: normalize, write g_A [b*s][h*64]
    const int b_ = bh >> 3, h = bh & 7;
#pragma unroll
    for (int mt = 0; mt < 2; mt++) {
        float inv0 = 1.f / lr[mt][0], inv1 = 1.f / lr[mt][1];
        int r0 = qt * 128 + mrow + 16 * mt + g;
        float* p0 = g_A + ((size_t)(b_ * SS + r0)) * HID + h * 64;
        float* p1 = p0 + (size_t)8 * HID;
#pragma unroll
        for (int nj = 0; nj < 8; nj++) {
            *(float2*)&p0[nj * 8 + 2 * tig] =
                make_float2(o[mt][nj][0] * inv0, o[mt][nj][1] * inv0);
            *(float2*)&p1[nj * 8 + 2 * tig] =
                make_float2(o[mt][nj][2] * inv1, o[mt][nj][3] * inv1);
        }
    }
}

// ===========================================================================
extern "C" void kernel_launch(void* const* d_in, const int* in_sizes, int n_in,
                              void* d_out, int out_size)
{
    const float* X  = (const float*)d_in[0];
    const float* Wq = (const float*)d_in[1];
    const float* bq = (const float*)d_in[2];
    const float* Wk = (const float*)d_in[3];
    const float* bk = (const float*)d_in[4];
    const float* Wv = (const float*)d_in[5];
    const float* bv = (const float*)d_in[6];
    const float* Wo = (const float*)d_in[7];
    const float* bo = (const float*)d_in[8];
    float* out = (float*)d_out;

    cudaFuncSetAttribute(qkv_mma,   cudaFuncAttributeMaxDynamicSharedMemorySize, PROJ_SMEM);
    cudaFuncSetAttribute(oproj_mma, cudaFuncAttributeMaxDynamicSharedMemorySize, PROJ_SMEM);
    cudaFuncSetAttribute(attn_mma,  cudaFuncAttributeMaxDynamicSharedMemorySize, ATTN_SMEM);

    qkv_mma<<<dim3(HID / 64, MM / 128, 3), 128, PROJ_SMEM>>>(X, Wq, bq, Wk, bk, Wv, bv);
    attn_mma<<<dim3(SS / 128, NB * NH), 128, ATTN_SMEM>>>();
    oproj_mma<<<dim3(VD / 64, MM / 128), 128, PROJ_SMEM>>>(Wo, bo, out);
}

// round 7
// speedup vs baseline: 1.4768x; 1.0928x over previous
#include <cuda_runtime.h>
#include <math.h>
#include <cstdint>

#define NB 4
#define SS 2048
#define TD 768
#define HID 512
#define NH 8
#define HD 64
#define VD 768
#define MM (NB*SS)   // 8192

// Scratch
__device__ float g_Q[NB*NH*SS*HD];   // [bh][s][d] (tf32-rounded)
__device__ float g_K[NB*NH*SS*HD];
__device__ float g_V[NB*NH*SS*HD];
__device__ float g_A[MM*HID];        // attended, [b*s][h*d] (tf32-rounded)
__device__ float g_Xr[MM*TD];        // tf32-rounded inputs/weights
__device__ float g_Wqr[TD*HID];
__device__ float g_Wkr[TD*HID];
__device__ float g_Wvr[TD*HID];
__device__ float g_Wor[HID*VD];

// ---------------------------------------------------------------------------
// Helpers (portable PTX, valid on plain sm_103 target)
// ---------------------------------------------------------------------------
__device__ __forceinline__ uint32_t smem_u32(const void* p) {
    uint32_t a;
    asm("{ .reg .u64 t; cvta.to.shared.u64 t, %1; cvt.u32.u64 %0, t; }" : "=r"(a) : "l"(p));
    return a;
}
__device__ __forceinline__ float tf32r(float x) {
    uint32_t u;
    asm("cvt.rna.tf32.f32 %0, %1;" : "=r"(u) : "f"(x));
    return __uint_as_float(u);
}
__device__ __forceinline__ float4 tf32r4(float4 v) {
    v.x = tf32r(v.x); v.y = tf32r(v.y); v.z = tf32r(v.z); v.w = tf32r(v.w);
    return v;
}
__device__ __forceinline__ void cp16(uint32_t dst, const void* src) {
    asm volatile("cp.async.ca.shared.global [%0], [%1], 16;" :: "r"(dst), "l"(src));
}
#define CP_COMMIT() asm volatile("cp.async.commit_group;" ::: "memory")
#define CP_WAIT0()  asm volatile("cp.async.wait_group 0;" ::: "memory")

// ldmatrix.x4 (tf32 trick: 8x4 tf32 tile == 8x8 b16 tile)
__device__ __forceinline__ void ldsm4(uint32_t* r, uint32_t a) {
    asm volatile("ldmatrix.sync.aligned.m8n8.x4.shared.b16 {%0,%1,%2,%3}, [%4];"
        : "=r"(r[0]), "=r"(r[1]), "=r"(r[2]), "=r"(r[3]) : "r"(a));
}
// A-fragment addresses: m16 x k8 tile at (m0,k0) in row-major [m][k], stride floats
__device__ __forceinline__ uint32_t a_addr(uint32_t base, int stride, int m0, int k0, int lane) {
    int sel = lane >> 3, r = lane & 7;
    return base + (((m0 + ((sel & 1) << 3) + r) * stride) + k0 + ((sel >> 1) << 2)) * 4;
}
// B-fragment addresses: two n-octets at (n0, k0) in [n][k] layout -> {b0,b1,b0',b1'}
__device__ __forceinline__ uint32_t b_addr(uint32_t base, int stride, int n0, int k0, int lane) {
    int sel = lane >> 3, r = lane & 7;
    return base + (((n0 + ((sel >> 1) << 3) + r) * stride) + k0 + ((sel & 1) << 2)) * 4;
}

// m16n8k8 tf32 MMA (g=lane>>2, tig=lane&3):
//  A: a0=[g][tig] a1=[g+8][tig] a2=[g][tig+4] a3=[g+8][tig+4]
//  B: b0=[k=tig][n=g] b1=[k=tig+4][n=g]
//  C: c0=[g][2tig] c1=[g][2tig+1] c2=[g+8][2tig] c3=[g+8][2tig+1]
__device__ __forceinline__ void mma8(float* c, const uint32_t* a, const uint32_t* b) {
    asm volatile(
        "mma.sync.aligned.m16n8k8.row.col.f32.tf32.tf32.f32 "
        "{%0,%1,%2,%3}, {%4,%5,%6,%7}, {%8,%9}, {%0,%1,%2,%3};"
        : "+f"(c[0]), "+f"(c[1]), "+f"(c[2]), "+f"(c[3])
        : "r"(a[0]), "r"(a[1]), "r"(a[2]), "r"(a[3]), "r"(b[0]), "r"(b[1]));
}

// ---------------------------------------------------------------------------
// Kernel 0: RNA-round inputs and weights once (hoists all in-loop cvt).
// ---------------------------------------------------------------------------
__global__ __launch_bounds__(256) void round_pre(
    const float* __restrict__ X,
    const float* __restrict__ Wq, const float* __restrict__ Wk,
    const float* __restrict__ Wv, const float* __restrict__ Wo)
{
    const int stride = gridDim.x * blockDim.x;
    const int i0 = blockIdx.x * blockDim.x + threadIdx.x;
    for (int i = i0; i < MM * TD / 4; i += stride)
        ((float4*)g_Xr)[i] = tf32r4(((const float4*)X)[i]);
    for (int i = i0; i < TD * HID / 4; i += stride) {
        ((float4*)g_Wqr)[i] = tf32r4(((const float4*)Wq)[i]);
        ((float4*)g_Wkr)[i] = tf32r4(((const float4*)Wk)[i]);
        ((float4*)g_Wvr)[i] = tf32r4(((const float4*)Wv)[i]);
        ((float4*)g_Wor)[i] = tf32r4(((const float4*)Wo)[i]);
    }
}

// ===========================================================================
// Projection GEMM body. CTA 128(M) x 64(N), BK=32, 128 threads (4 warps),
// warp tile 64x32. cp.async double-buffered. Data pre-rounded: NO in-loop cvt.
//   A-frags: ldmatrix from X [m][k] (stride 36, conflict-free)
//   B-frags: scalar LDS from W [k][n] (stride 72, banks 8*tig+g, conflict-free)
// smem floats: X[2][128][36] | W[2][32][72]
// ===========================================================================
#define PX0 0
#define PX1 4608
#define PW0 9216
#define PW1 11520
#define PROJ_SMEM (13824 * 4)

__device__ __forceinline__ void proj_issue(
    uint32_t sb, int buf, int kt,
    const float* __restrict__ A, int lda,
    const float* __restrict__ W, int ldw,
    int m0, int n0, int t)
{
    uint32_t xd = sb + (buf ? PX1 : PX0) * 4;
#pragma unroll
    for (int it = 0; it < 8; it++) {
        int i = t + it * 128;
        int r = i >> 3, fg = i & 7;
        cp16(xd + (r * 36 + fg * 4) * 4, &A[(size_t)(m0 + r) * lda + kt + fg * 4]);
    }
    uint32_t wd = sb + (buf ? PW1 : PW0) * 4;
#pragma unroll
    for (int it = 0; it < 4; it++) {
        int i = t + it * 128;
        int r = i >> 4, fg = i & 15;
        cp16(wd + (r * 72 + fg * 4) * 4, &W[(size_t)(kt + r) * ldw + n0 + fg * 4]);
    }
}

__device__ __forceinline__ void proj_body(
    float* sm, uint32_t sb,
    const float* __restrict__ A, int lda,
    const float* __restrict__ W, int ldw,
    int kdim, int m0, int n0, float acc[4][4][4])
{
    const int t = threadIdx.x;
    const int w = t >> 5, lane = t & 31, g = lane >> 2, tig = lane & 3;
    const int mw = (w >> 1) * 64, nw = (w & 1) * 32;

#pragma unroll
    for (int mi = 0; mi < 4; mi++)
#pragma unroll
        for (int nj = 0; nj < 4; nj++)
#pragma unroll
            for (int r = 0; r < 4; r++) acc[mi][nj][r] = 0.f;

    const int nc = kdim >> 5;
    proj_issue(sb, 0, 0, A, lda, W, ldw, m0, n0, t);
    CP_COMMIT();

    for (int c = 0; c < nc; c++) {
        CP_WAIT0();
        __syncthreads();
        if (c + 1 < nc) {
            proj_issue(sb, (c + 1) & 1, (c + 1) << 5, A, lda, W, ldw, m0, n0, t);
            CP_COMMIT();
        }
        uint32_t xb = sb + ((c & 1) ? PX1 : PX0) * 4;
        const float* ws = sm + ((c & 1) ? PW1 : PW0);

#pragma unroll
        for (int ks = 0; ks < 4; ks++) {
            uint32_t af[4][4];
#pragma unroll
            for (int mi = 0; mi < 4; mi++)
                ldsm4(af[mi], a_addr(xb, 36, mw + 16 * mi, ks * 8, lane));
#pragma unroll
            for (int nj = 0; nj < 4; nj++) {
                uint32_t bf[2];
                bf[0] = __float_as_uint(ws[(ks * 8 + tig) * 72 + nw + nj * 8 + g]);
                bf[1] = __float_as_uint(ws[(ks * 8 + tig + 4) * 72 + nw + nj * 8 + g]);
#pragma unroll
                for (int mi = 0; mi < 4; mi++)
                    mma8(acc[mi][nj], af[mi], bf);
            }
        }
    }
}

// ---------------------------------------------------------------------------
// Kernel 1: fused QKV projection -> [bh][s][d], epilogue tf32-rounds outputs
// ---------------------------------------------------------------------------
__global__ __launch_bounds__(128) void qkv_mma(
    const float* __restrict__ bq, const float* __restrict__ bk,
    const float* __restrict__ bv)
{
    extern __shared__ float sm[];
    uint32_t sb = smem_u32(sm);

    const int z = blockIdx.z;
    const float* W    = (z == 0) ? g_Wqr : (z == 1) ? g_Wkr : g_Wvr;
    const float* bias = (z == 0) ? bq : (z == 1) ? bk : bv;
    float* out        = (z == 0) ? g_Q : (z == 1) ? g_K : g_V;

    const int m0 = blockIdx.y * 128;
    const int n0 = blockIdx.x * 64;
    const int h  = blockIdx.x;

    float acc[4][4][4];
    proj_body(sm, sb, g_Xr, TD, W, HID, TD, m0, n0, acc);

    const int t = threadIdx.x;
    const int w = t >> 5, lane = t & 31, g = lane >> 2, tig = lane & 3;
    const int mw = (w >> 1) * 64, nw = (w & 1) * 32;

#pragma unroll
    for (int mi = 0; mi < 4; mi++) {
        int r = m0 + mw + 16 * mi + g;
        int b_ = r >> 11, s_ = r & 2047;
        float* base0 = out + ((((size_t)(b_ * NH + h)) * SS + s_) << 6);
        float* base1 = base0 + (8 << 6);
#pragma unroll
        for (int nj = 0; nj < 4; nj++) {
            int col = nw + nj * 8 + 2 * tig;
            float2 bb = *(const float2*)&bias[n0 + col];
            *(float2*)&base0[col] = make_float2(tf32r(acc[mi][nj][0] + bb.x),
                                                tf32r(acc[mi][nj][1] + bb.y));
            *(float2*)&base1[col] = make_float2(tf32r(acc[mi][nj][2] + bb.x),
                                                tf32r(acc[mi][nj][3] + bb.y));
        }
    }
}

// ---------------------------------------------------------------------------
// Kernel 3: output projection  out = g_A @ Wo + bo (fp32 output, no rounding)
// ---------------------------------------------------------------------------
__global__ __launch_bounds__(128) void oproj_mma(
    const float* __restrict__ bo, float* __restrict__ out)
{
    extern __shared__ float sm[];
    uint32_t sb = smem_u32(sm);
    const int m0 = blockIdx.y * 128;
    const int n0 = blockIdx.x * 64;

    float acc[4][4][4];
    proj_body(sm, sb, g_A, HID, g_Wor, VD, HID, m0, n0, acc);

    const int t = threadIdx.x;
    const int w = t >> 5, lane = t & 31, g = lane >> 2, tig = lane & 3;
    const int mw = (w >> 1) * 64, nw = (w & 1) * 32;

#pragma unroll
    for (int mi = 0; mi < 4; mi++) {
        int r = m0 + mw + 16 * mi + g;
        float* base0 = out + (size_t)r * VD + n0;
        float* base1 = base0 + (size_t)8 * VD;
#pragma unroll
        for (int nj = 0; nj < 4; nj++) {
            int col = nw + nj * 8 + 2 * tig;
            float2 bb = *(const float2*)&bo[n0 + col];
            *(float2*)&base0[col] = make_float2(acc[mi][nj][0] + bb.x, acc[mi][nj][1] + bb.y);
            *(float2*)&base1[col] = make_float2(acc[mi][nj][2] + bb.x, acc[mi][nj][3] + bb.y);
        }
    }
}

// ===========================================================================
// Kernel 2: flash attention. 128 threads (4 warps), q-tile 128 -> 32 rows
// per warp (2 m-tiles). Key tile 32, cp.async double-buffered K/V.
// Q/K/V pre-rounded -> zero in-loop cvt; P rounded at store only.
// smem floats: Q[128][68] | K[2][32][68] | V[2][32][72] | P[128][36]
// ===========================================================================
#define AQ  0
#define AK0 8704
#define AK1 10880
#define AV0 13056
#define AV1 15360
#define AP  17664
#define ATTN_SMEM (22272 * 4)
#define NIT (SS / 32)   // 64 key tiles

__device__ __forceinline__ void attn_issue(
    uint32_t sb, int buf, const float* __restrict__ Kg,
    const float* __restrict__ Vg, int kt, int t)
{
    uint32_t kd = sb + (buf ? AK1 : AK0) * 4;
    uint32_t vd = sb + (buf ? AV1 : AV0) * 4;
    const float* Kt = Kg + (size_t)kt * 32 * 64;
    const float* Vt = Vg + (size_t)kt * 32 * 64;
#pragma unroll
    for (int it = 0; it < 4; it++) {
        int i = t + it * 128;
        int r = i >> 4, fg = i & 15;
        cp16(kd + (r * 68 + fg * 4) * 4, &Kt[r * 64 + fg * 4]);
        cp16(vd + (r * 72 + fg * 4) * 4, &Vt[r * 64 + fg * 4]);
    }
}

__global__ __launch_bounds__(128, 1) void attn_mma()
{
    extern __shared__ float sm[];
    uint32_t sb = smem_u32(sm);
    const int t = threadIdx.x;
    const int w = t >> 5, lane = t & 31, g = lane >> 2, tig = lane & 3;
    const int qt = blockIdx.x, bh = blockIdx.y;
    const int mrow = w * 32;

    const float* Qg = g_Q + (size_t)bh * SS * HD;
    const float* Kg = g_K + (size_t)bh * SS * HD;
    const float* Vg = g_V + (size_t)bh * SS * HD;

    attn_issue(sb, 0, Kg, Vg, 0, t);
    CP_COMMIT();

    // Load Q tile [128][64] (already rounded)
#pragma unroll
    for (int it = 0; it < 16; it++) {
        int i = t + it * 128;
        int r = i >> 4, fg = i & 15;
        *(float4*)&sm[AQ + r * 68 + fg * 4] =
            *(const float4*)&Qg[(size_t)(qt * 128 + r) * 64 + fg * 4];
    }

    float o[2][8][4];
#pragma unroll
    for (int mt = 0; mt < 2; mt++)
#pragma unroll
        for (int nj = 0; nj < 8; nj++)
#pragma unroll
            for (int r = 0; r < 4; r++) o[mt][nj][r] = 0.f;
    float mr[2][2] = {{-1e30f, -1e30f}, {-1e30f, -1e30f}};
    float lr[2][2] = {{0.f, 0.f}, {0.f, 0.f}};

    for (int kt = 0; kt < NIT; kt++) {
        CP_WAIT0();
        __syncthreads();
        if (kt + 1 < NIT) {
            attn_issue(sb, (kt + 1) & 1, Kg, Vg, kt + 1, t);
            CP_COMMIT();
        }
        uint32_t kb = sb + ((kt & 1) ? AK1 : AK0) * 4;

        // S = Q K^T  (32 rows x 32 keys per warp)
        float s[2][4][4];
#pragma unroll
        for (int mt = 0; mt < 2; mt++)
#pragma unroll
            for (int nj = 0; nj < 4; nj++)
#pragma unroll
                for (int r = 0; r < 4; r++) s[mt][nj][r] = 0.f;

#pragma unroll
        for (int ks = 0; ks < 8; ks++) {
            uint32_t qa0[4], qa1[4];
            ldsm4(qa0, a_addr(sb, 68, mrow, ks * 8, lane));
            ldsm4(qa1, a_addr(sb, 68, mrow + 16, ks * 8, lane));
#pragma unroll
            for (int p = 0; p < 2; p++) {
                uint32_t bf[4];
                ldsm4(bf, b_addr(kb, 68, p * 16, ks * 8, lane));
                mma8(s[0][p * 2],     qa0, bf);
                mma8(s[0][p * 2 + 1], qa0, bf + 2);
                mma8(s[1][p * 2],     qa1, bf);
                mma8(s[1][p * 2 + 1], qa1, bf + 2);
            }
        }

        // Online softmax: 4 row-groups (mt x {g, g+8}), quad reduction
        float corr[2][2];
#pragma unroll
        for (int mt = 0; mt < 2; mt++) {
            float mx0 = mr[mt][0], mx1 = mr[mt][1];
#pragma unroll
            for (int nj = 0; nj < 4; nj++) {
                s[mt][nj][0] *= 0.125f; s[mt][nj][1] *= 0.125f;
                s[mt][nj][2] *= 0.125f; s[mt][nj][3] *= 0.125f;
                mx0 = fmaxf(mx0, fmaxf(s[mt][nj][0], s[mt][nj][1]));
                mx1 = fmaxf(mx1, fmaxf(s[mt][nj][2], s[mt][nj][3]));
            }
            mx0 = fmaxf(mx0, __shfl_xor_sync(0xffffffffu, mx0, 1));
            mx0 = fmaxf(mx0, __shfl_xor_sync(0xffffffffu, mx0, 2));
            mx1 = fmaxf(mx1, __shfl_xor_sync(0xffffffffu, mx1, 1));
            mx1 = fmaxf(mx1, __shfl_xor_sync(0xffffffffu, mx1, 2));

            corr[mt][0] = __expf(mr[mt][0] - mx0);
            corr[mt][1] = __expf(mr[mt][1] - mx1);
            float ls0 = 0.f, ls1 = 0.f;
            int row0 = mrow + 16 * mt + g;
#pragma unroll
            for (int nj = 0; nj < 4; nj++) {
                float p0 = __expf(s[mt][nj][0] - mx0);
                float p1 = __expf(s[mt][nj][1] - mx0);
                float p2 = __expf(s[mt][nj][2] - mx1);
                float p3 = __expf(s[mt][nj][3] - mx1);
                ls0 += p0 + p1;
                ls1 += p2 + p3;
                *(float2*)&sm[AP + row0 * 36 + nj * 8 + 2 * tig] =
                    make_float2(tf32r(p0), tf32r(p1));
                *(float2*)&sm[AP + (row0 + 8) * 36 + nj * 8 + 2 * tig] =
                    make_float2(tf32r(p2), tf32r(p3));
            }
            ls0 += __shfl_xor_sync(0xffffffffu, ls0, 1);
            ls0 += __shfl_xor_sync(0xffffffffu, ls0, 2);
            ls1 += __shfl_xor_sync(0xffffffffu, ls1, 1);
            ls1 += __shfl_xor_sync(0xffffffffu, ls1, 2);
            lr[mt][0] = lr[mt][0] * corr[mt][0] + ls0;
            lr[mt][1] = lr[mt][1] * corr[mt][1] + ls1;
            mr[mt][0] = mx0; mr[mt][1] = mx1;

#pragma unroll
            for (int nj = 0; nj < 8; nj++) {
                o[mt][nj][0] *= corr[mt][0]; o[mt][nj][1] *= corr[mt][0];
                o[mt][nj][2] *= corr[mt][1]; o[mt][nj][3] *= corr[mt][1];
            }
        }
        __syncwarp();   // P rows are warp-private

        // O += P V   (keys = 4 k-steps of 8; V [k][n] scalar B-frags)
        uint32_t pb = sb + AP * 4;
        const float* vs = sm + ((kt & 1) ? AV1 : AV0);
#pragma unroll
        for (int ks = 0; ks < 4; ks++) {
            uint32_t pa0[4], pa1[4];
            ldsm4(pa0, a_addr(pb, 36, mrow, ks * 8, lane));
            ldsm4(pa1, a_addr(pb, 36, mrow + 16, ks * 8, lane));
#pragma unroll
            for (int nj = 0; nj < 8; nj++) {
                uint32_t bf[2];
                bf[0] = __float_as_uint(vs[(ks * 8 + tig) * 72 + nj * 8 + g]);
                bf[1] = __float_as_uint(vs[(ks * 8 + tig + 4) * 72 + nj * 8 + g]);
                mma8(o[0][nj], pa0, bf);
                mma8(o[1][nj], pa1, bf);
            }
        }
    }

    // Epilogue: normalize, round, write g_A [b*s][h*64]
    const int b_ = bh >> 3, h = bh & 7;
#pragma unroll
    for (int mt = 0; mt < 2; mt++) {
        float inv0 = 1.f / lr[mt][0], inv1 = 1.f / lr[mt][1];
        int r0 = qt * 128 + mrow + 16 * mt + g;
        float* p0 = g_A + ((size_t)(b_ * SS + r0)) * HID + h * 64;
        float* p1 = p0 + (size_t)8 * HID;
#pragma unroll
        for (int nj = 0; nj < 8; nj++) {
            *(float2*)&p0[nj * 8 + 2 * tig] =
                make_float2(tf32r(o[mt][nj][0] * inv0), tf32r(o[mt][nj][1] * inv0));
            *(float2*)&p1[nj * 8 + 2 * tig] =
                make_float2(tf32r(o[mt][nj][2] * inv1), tf32r(o[mt][nj][3] * inv1));
        }
    }
}

// ===========================================================================
extern "C" void kernel_launch(void* const* d_in, const int* in_sizes, int n_in,
                              void* d_out, int out_size)
{
    const float* X  = (const float*)d_in[0];
    const float* Wq = (const float*)d_in[1];
    const float* bq = (const float*)d_in[2];
    const float* Wk = (const float*)d_in[3];
    const float* bk = (const float*)d_in[4];
    const float* Wv = (const float*)d_in[5];
    const float* bv = (const float*)d_in[6];
    const float* Wo = (const float*)d_in[7];
    const float* bo = (const float*)d_in[8];
    float* out = (float*)d_out;

    cudaFuncSetAttribute(qkv_mma,   cudaFuncAttributeMaxDynamicSharedMemorySize, PROJ_SMEM);
    cudaFuncSetAttribute(oproj_mma, cudaFuncAttributeMaxDynamicSharedMemorySize, PROJ_SMEM);
    cudaFuncSetAttribute(attn_mma,  cudaFuncAttributeMaxDynamicSharedMemorySize, ATTN_SMEM);

    round_pre<<<1184, 256>>>(X, Wq, Wk, Wv, Wo);
    qkv_mma<<<dim3(HID / 64, MM / 128, 3), 128, PROJ_SMEM>>>(bq, bk, bv);
    attn_mma<<<dim3(SS / 128, NB * NH), 128, ATTN_SMEM>>>();
    oproj_mma<<<dim3(VD / 64, MM / 128), 128, PROJ_SMEM>>>(bo, out);
}

// round 8
// speedup vs baseline: 1.5245x; 1.0323x over previous
#include <cuda_runtime.h>
#include <math.h>
#include <cstdint>

#define NB 4
#define SS 2048
#define TD 768
#define HID 512
#define NH 8
#define HD 64
#define VD 768
#define MM (NB*SS)   // 8192

// Scratch
__device__ float g_Q[NB*NH*SS*HD];   // [bh][s][d] (tf32-rounded)
__device__ float g_K[NB*NH*SS*HD];
__device__ float g_V[NB*NH*SS*HD];
__device__ float g_A[MM*HID];        // attended, [b*s][h*d] (tf32-rounded)
__device__ float g_Xr[MM*TD];        // tf32-rounded inputs/weights
__device__ float g_Wqr[TD*HID];
__device__ float g_Wkr[TD*HID];
__device__ float g_Wvr[TD*HID];
__device__ float g_Wor[HID*VD];

// ---------------------------------------------------------------------------
// Helpers (portable PTX, valid on plain sm_103 target)
// ---------------------------------------------------------------------------
__device__ __forceinline__ uint32_t smem_u32(const void* p) {
    uint32_t a;
    asm("{ .reg .u64 t; cvta.to.shared.u64 t, %1; cvt.u32.u64 %0, t; }" : "=r"(a) : "l"(p));
    return a;
}
__device__ __forceinline__ float tf32r(float x) {
    uint32_t u;
    asm("cvt.rna.tf32.f32 %0, %1;" : "=r"(u) : "f"(x));
    return __uint_as_float(u);
}
__device__ __forceinline__ float4 tf32r4(float4 v) {
    v.x = tf32r(v.x); v.y = tf32r(v.y); v.z = tf32r(v.z); v.w = tf32r(v.w);
    return v;
}
__device__ __forceinline__ void cp16(uint32_t dst, const void* src) {
    asm volatile("cp.async.ca.shared.global [%0], [%1], 16;" :: "r"(dst), "l"(src));
}
#define CP_COMMIT() asm volatile("cp.async.commit_group;" ::: "memory")
#define CP_WAIT0()  asm volatile("cp.async.wait_group 0;" ::: "memory")

// ldmatrix.x4 (tf32 trick: 8x4 tf32 tile == 8x8 b16 tile)
__device__ __forceinline__ void ldsm4(uint32_t* r, uint32_t a) {
    asm volatile("ldmatrix.sync.aligned.m8n8.x4.shared.b16 {%0,%1,%2,%3}, [%4];"
        : "=r"(r[0]), "=r"(r[1]), "=r"(r[2]), "=r"(r[3]) : "r"(a));
}
// A-fragment addresses: m16 x k8 tile at (m0,k0) in row-major [m][k], stride floats
__device__ __forceinline__ uint32_t a_addr(uint32_t base, int stride, int m0, int k0, int lane) {
    int sel = lane >> 3, r = lane & 7;
    return base + (((m0 + ((sel & 1) << 3) + r) * stride) + k0 + ((sel >> 1) << 2)) * 4;
}
// B-fragment addresses: two n-octets at (n0, k0) in [n][k] layout -> {b0,b1,b0',b1'}
__device__ __forceinline__ uint32_t b_addr(uint32_t base, int stride, int n0, int k0, int lane) {
    int sel = lane >> 3, r = lane & 7;
    return base + (((n0 + ((sel >> 1) << 3) + r) * stride) + k0 + ((sel & 1) << 2)) * 4;
}

// m16n8k8 tf32 MMA (g=lane>>2, tig=lane&3):
//  A: a0=[g][tig] a1=[g+8][tig] a2=[g][tig+4] a3=[g+8][tig+4]
//  B: b0=[k=tig][n=g] b1=[k=tig+4][n=g]
//  C: c0=[g][2tig] c1=[g][2tig+1] c2=[g+8][2tig] c3=[g+8][2tig+1]
__device__ __forceinline__ void mma8(float* c, const uint32_t* a, const uint32_t* b) {
    asm volatile(
        "mma.sync.aligned.m16n8k8.row.col.f32.tf32.tf32.f32 "
        "{%0,%1,%2,%3}, {%4,%5,%6,%7}, {%8,%9}, {%0,%1,%2,%3};"
        : "+f"(c[0]), "+f"(c[1]), "+f"(c[2]), "+f"(c[3])
        : "r"(a[0]), "r"(a[1]), "r"(a[2]), "r"(a[3]), "r"(b[0]), "r"(b[1]));
}

// ---------------------------------------------------------------------------
// Kernel 0: RNA-round inputs and weights once.
// ---------------------------------------------------------------------------
__global__ __launch_bounds__(256) void round_pre(
    const float* __restrict__ X,
    const float* __restrict__ Wq, const float* __restrict__ Wk,
    const float* __restrict__ Wv, const float* __restrict__ Wo)
{
    const int stride = gridDim.x * blockDim.x;
    const int i0 = blockIdx.x * blockDim.x + threadIdx.x;
    for (int i = i0; i < MM * TD / 4; i += stride)
        ((float4*)g_Xr)[i] = tf32r4(((const float4*)X)[i]);
    for (int i = i0; i < TD * HID / 4; i += stride) {
        ((float4*)g_Wqr)[i] = tf32r4(((const float4*)Wq)[i]);
        ((float4*)g_Wkr)[i] = tf32r4(((const float4*)Wk)[i]);
        ((float4*)g_Wvr)[i] = tf32r4(((const float4*)Wv)[i]);
        ((float4*)g_Wor)[i] = tf32r4(((const float4*)Wo)[i]);
    }
}

// ===========================================================================
// Projection GEMM body. CTA 128(M) x 128(N), BK=32, 128 threads (4 warps),
// warp tile 64x64 (acc = 128 regs: 1.0 smem-wavefront per MMA).
//   A-frags: ldmatrix from X [m][k] (stride 36, conflict-free)
//   B-frags: scalar LDS from W [k][n] (stride 136, banks 8(tig+nj)+g, CF)
// smem floats: X[2][128][36] | W[2][32][136]
// ===========================================================================
#define PX0 0
#define PX1 4608
#define PW0 9216
#define PW1 13568
#define PROJ_SMEM (17920 * 4)

__device__ __forceinline__ void proj_issue(
    uint32_t sb, int buf, int kt,
    const float* __restrict__ A, int lda,
    const float* __restrict__ W, int ldw,
    int m0, int n0, int t)
{
    uint32_t xd = sb + (buf ? PX1 : PX0) * 4;
#pragma unroll
    for (int it = 0; it < 8; it++) {
        int i = t + it * 128;
        int r = i >> 3, fg = i & 7;
        cp16(xd + (r * 36 + fg * 4) * 4, &A[(size_t)(m0 + r) * lda + kt + fg * 4]);
    }
    uint32_t wd = sb + (buf ? PW1 : PW0) * 4;
#pragma unroll
    for (int it = 0; it < 8; it++) {
        int i = t + it * 128;
        int r = i >> 5, fg = i & 31;
        cp16(wd + (r * 136 + fg * 4) * 4, &W[(size_t)(kt + r) * ldw + n0 + fg * 4]);
    }
}

__device__ __forceinline__ void proj_body(
    float* sm, uint32_t sb,
    const float* __restrict__ A, int lda,
    const float* __restrict__ W, int ldw,
    int kdim, int m0, int n0, float acc[4][8][4])
{
    const int t = threadIdx.x;
    const int w = t >> 5, lane = t & 31, g = lane >> 2, tig = lane & 3;
    const int mw = (w >> 1) * 64, nw = (w & 1) * 64;

#pragma unroll
    for (int mi = 0; mi < 4; mi++)
#pragma unroll
        for (int nj = 0; nj < 8; nj++)
#pragma unroll
            for (int r = 0; r < 4; r++) acc[mi][nj][r] = 0.f;

    const int nc = kdim >> 5;
    proj_issue(sb, 0, 0, A, lda, W, ldw, m0, n0, t);
    CP_COMMIT();

    for (int c = 0; c < nc; c++) {
        CP_WAIT0();
        __syncthreads();
        if (c + 1 < nc) {
            proj_issue(sb, (c + 1) & 1, (c + 1) << 5, A, lda, W, ldw, m0, n0, t);
            CP_COMMIT();
        }
        uint32_t xb = sb + ((c & 1) ? PX1 : PX0) * 4;
        const float* ws = sm + ((c & 1) ? PW1 : PW0);

#pragma unroll
        for (int ks = 0; ks < 4; ks++) {
            uint32_t af[4][4];
#pragma unroll
            for (int mi = 0; mi < 4; mi++)
                ldsm4(af[mi], a_addr(xb, 36, mw + 16 * mi, ks * 8, lane));
#pragma unroll
            for (int nj = 0; nj < 8; nj++) {
                uint32_t bf[2];
                bf[0] = __float_as_uint(ws[(ks * 8 + tig) * 136 + nw + nj * 8 + g]);
                bf[1] = __float_as_uint(ws[(ks * 8 + tig + 4) * 136 + nw + nj * 8 + g]);
#pragma unroll
                for (int mi = 0; mi < 4; mi++)
                    mma8(acc[mi][nj], af[mi], bf);
            }
        }
    }
}

// ---------------------------------------------------------------------------
// Kernel 1: fused QKV projection -> [bh][s][d], epilogue tf32-rounds outputs
// ---------------------------------------------------------------------------
__global__ __launch_bounds__(128) void qkv_mma(
    const float* __restrict__ bq, const float* __restrict__ bk,
    const float* __restrict__ bv)
{
    extern __shared__ float sm[];
    uint32_t sb = smem_u32(sm);

    const int z = blockIdx.z;
    const float* W    = (z == 0) ? g_Wqr : (z == 1) ? g_Wkr : g_Wvr;
    const float* bias = (z == 0) ? bq : (z == 1) ? bk : bv;
    float* out        = (z == 0) ? g_Q : (z == 1) ? g_K : g_V;

    const int m0 = blockIdx.y * 128;
    const int n0 = blockIdx.x * 128;

    float acc[4][8][4];
    proj_body(sm, sb, g_Xr, TD, W, HID, TD, m0, n0, acc);

    const int t = threadIdx.x;
    const int w = t >> 5, lane = t & 31, g = lane >> 2, tig = lane & 3;
    const int mw = (w >> 1) * 64, nw = (w & 1) * 64;

#pragma unroll
    for (int mi = 0; mi < 4; mi++) {
        int r = m0 + mw + 16 * mi + g;
        int b_ = r >> 11, s_ = r & 2047;
#pragma unroll
        for (int nj = 0; nj < 8; nj++) {
            int cg = n0 + nw + nj * 8 + 2 * tig;
            int h = cg >> 6, d = cg & 63;
            float* base0 = out + ((((size_t)(b_ * NH + h)) * SS + s_) << 6) + d;
            float* base1 = base0 + (8 << 6);
            float2 bb = *(const float2*)&bias[cg];
            *(float2*)base0 = make_float2(tf32r(acc[mi][nj][0] + bb.x),
                                          tf32r(acc[mi][nj][1] + bb.y));
            *(float2*)base1 = make_float2(tf32r(acc[mi][nj][2] + bb.x),
                                          tf32r(acc[mi][nj][3] + bb.y));
        }
    }
}

// ---------------------------------------------------------------------------
// Kernel 3: output projection  out = g_A @ Wo + bo (fp32 output)
// ---------------------------------------------------------------------------
__global__ __launch_bounds__(128) void oproj_mma(
    const float* __restrict__ bo, float* __restrict__ out)
{
    extern __shared__ float sm[];
    uint32_t sb = smem_u32(sm);
    const int m0 = blockIdx.y * 128;
    const int n0 = blockIdx.x * 128;

    float acc[4][8][4];
    proj_body(sm, sb, g_A, HID, g_Wor, VD, HID, m0, n0, acc);

    const int t = threadIdx.x;
    const int w = t >> 5, lane = t & 31, g = lane >> 2, tig = lane & 3;
    const int mw = (w >> 1) * 64, nw = (w & 1) * 64;

#pragma unroll
    for (int mi = 0; mi < 4; mi++) {
        int r = m0 + mw + 16 * mi + g;
        float* base0 = out + (size_t)r * VD + n0 + nw;
        float* base1 = base0 + (size_t)8 * VD;
#pragma unroll
        for (int nj = 0; nj < 8; nj++) {
            int col = nj * 8 + 2 * tig;
            float2 bb = *(const float2*)&bo[n0 + nw + col];
            *(float2*)&base0[col] = make_float2(acc[mi][nj][0] + bb.x, acc[mi][nj][1] + bb.y);
            *(float2*)&base1[col] = make_float2(acc[mi][nj][2] + bb.x, acc[mi][nj][3] + bb.y);
        }
    }
}

// ===========================================================================
// Kernel 2: flash attention. 128 threads (4 warps), q-tile 128 (32 rows/warp),
// key tile 64. Q-fragments persist in REGISTERS (Q staged through the K/V
// region then freed). One softmax pass per 64 keys. cp.async double-buffered.
// smem floats: K[2][64][68] | V[2][64][72] | P[128][68]
// ===========================================================================
#define AK0 0
#define AK1 4352
#define AV0 8704
#define AV1 13312
#define AP  17920
#define ATTN_SMEM (26624 * 4)
#define NIT (SS / 64)   // 32 key tiles

__device__ __forceinline__ void attn_issue(
    uint32_t sb, int buf, const float* __restrict__ Kg,
    const float* __restrict__ Vg, int kt, int t)
{
    uint32_t kd = sb + (buf ? AK1 : AK0) * 4;
    uint32_t vd = sb + (buf ? AV1 : AV0) * 4;
    const float* Kt = Kg + (size_t)kt * 64 * 64;
    const float* Vt = Vg + (size_t)kt * 64 * 64;
#pragma unroll
    for (int it = 0; it < 8; it++) {
        int i = t + it * 128;
        int r = i >> 4, fg = i & 15;
        cp16(kd + (r * 68 + fg * 4) * 4, &Kt[r * 64 + fg * 4]);
        cp16(vd + (r * 72 + fg * 4) * 4, &Vt[r * 64 + fg * 4]);
    }
}

__global__ __launch_bounds__(128, 1) void attn_mma()
{
    extern __shared__ float sm[];
    uint32_t sb = smem_u32(sm);
    const int t = threadIdx.x;
    const int w = t >> 5, lane = t & 31, g = lane >> 2, tig = lane & 3;
    const int qt = blockIdx.x, bh = blockIdx.y;
    const int mrow = w * 32;

    const float* Qg = g_Q + (size_t)bh * SS * HD;
    const float* Kg = g_K + (size_t)bh * SS * HD;
    const float* Vg = g_V + (size_t)bh * SS * HD;

    // Stage Q [128][68] into the K region, extract frags to regs, then free.
#pragma unroll
    for (int it = 0; it < 16; it++) {
        int i = t + it * 128;
        int r = i >> 4, fg = i & 15;
        *(float4*)&sm[r * 68 + fg * 4] =
            *(const float4*)&Qg[(size_t)(qt * 128 + r) * 64 + fg * 4];
    }
    __syncthreads();
    uint32_t qa[8][2][4];
#pragma unroll
    for (int ks = 0; ks < 8; ks++) {
        ldsm4(qa[ks][0], a_addr(sb, 68, mrow, ks * 8, lane));
        ldsm4(qa[ks][1], a_addr(sb, 68, mrow + 16, ks * 8, lane));
    }
    __syncthreads();   // Q reads done; K/V region may be overwritten

    attn_issue(sb, 0, Kg, Vg, 0, t);
    CP_COMMIT();

    float o[2][8][4];
#pragma unroll
    for (int mt = 0; mt < 2; mt++)
#pragma unroll
        for (int nj = 0; nj < 8; nj++)
#pragma unroll
            for (int r = 0; r < 4; r++) o[mt][nj][r] = 0.f;
    float mr[2][2] = {{-1e30f, -1e30f}, {-1e30f, -1e30f}};
    float lr[2][2] = {{0.f, 0.f}, {0.f, 0.f}};

    for (int kt = 0; kt < NIT; kt++) {
        CP_WAIT0();
        __syncthreads();
        if (kt + 1 < NIT) {
            attn_issue(sb, (kt + 1) & 1, Kg, Vg, kt + 1, t);
            CP_COMMIT();
        }
        uint32_t kb = sb + ((kt & 1) ? AK1 : AK0) * 4;

        // S = Q K^T  (32 rows x 64 keys per warp; Q from registers)
        float s[2][8][4];
#pragma unroll
        for (int mt = 0; mt < 2; mt++)
#pragma unroll
            for (int nj = 0; nj < 8; nj++)
#pragma unroll
                for (int r = 0; r < 4; r++) s[mt][nj][r] = 0.f;

#pragma unroll
        for (int ks = 0; ks < 8; ks++)
#pragma unroll
            for (int p = 0; p < 4; p++) {
                uint32_t bf[4];
                ldsm4(bf, b_addr(kb, 68, p * 16, ks * 8, lane));
                mma8(s[0][p * 2],     qa[ks][0], bf);
                mma8(s[0][p * 2 + 1], qa[ks][0], bf + 2);
                mma8(s[1][p * 2],     qa[ks][1], bf);
                mma8(s[1][p * 2 + 1], qa[ks][1], bf + 2);
            }

        // Online softmax (one pass per 64 keys)
        float corr[2][2];
#pragma unroll
        for (int mt = 0; mt < 2; mt++) {
            float mx0 = mr[mt][0], mx1 = mr[mt][1];
#pragma unroll
            for (int nj = 0; nj < 8; nj++) {
                s[mt][nj][0] *= 0.125f; s[mt][nj][1] *= 0.125f;
                s[mt][nj][2] *= 0.125f; s[mt][nj][3] *= 0.125f;
                mx0 = fmaxf(mx0, fmaxf(s[mt][nj][0], s[mt][nj][1]));
                mx1 = fmaxf(mx1, fmaxf(s[mt][nj][2], s[mt][nj][3]));
            }
            mx0 = fmaxf(mx0, __shfl_xor_sync(0xffffffffu, mx0, 1));
            mx0 = fmaxf(mx0, __shfl_xor_sync(0xffffffffu, mx0, 2));
            mx1 = fmaxf(mx1, __shfl_xor_sync(0xffffffffu, mx1, 1));
            mx1 = fmaxf(mx1, __shfl_xor_sync(0xffffffffu, mx1, 2));

            corr[mt][0] = __expf(mr[mt][0] - mx0);
            corr[mt][1] = __expf(mr[mt][1] - mx1);
            float ls0 = 0.f, ls1 = 0.f;
            int row0 = mrow + 16 * mt + g;
#pragma unroll
            for (int nj = 0; nj < 8; nj++) {
                float p0 = __expf(s[mt][nj][0] - mx0);
                float p1 = __expf(s[mt][nj][1] - mx0);
                float p2 = __expf(s[mt][nj][2] - mx1);
                float p3 = __expf(s[mt][nj][3] - mx1);
                ls0 += p0 + p1;
                ls1 += p2 + p3;
                *(float2*)&sm[AP + row0 * 68 + nj * 8 + 2 * tig] =
                    make_float2(tf32r(p0), tf32r(p1));
                *(float2*)&sm[AP + (row0 + 8) * 68 + nj * 8 + 2 * tig] =
                    make_float2(tf32r(p2), tf32r(p3));
            }
            ls0 += __shfl_xor_sync(0xffffffffu, ls0, 1);
            ls0 += __shfl_xor_sync(0xffffffffu, ls0, 2);
            ls1 += __shfl_xor_sync(0xffffffffu, ls1, 1);
            ls1 += __shfl_xor_sync(0xffffffffu, ls1, 2);
            lr[mt][0] = lr[mt][0] * corr[mt][0] + ls0;
            lr[mt][1] = lr[mt][1] * corr[mt][1] + ls1;
            mr[mt][0] = mx0; mr[mt][1] = mx1;

#pragma unroll
            for (int nj = 0; nj < 8; nj++) {
                o[mt][nj][0] *= corr[mt][0]; o[mt][nj][1] *= corr[mt][0];
                o[mt][nj][2] *= corr[mt][1]; o[mt][nj][3] *= corr[mt][1];
            }
        }
        __syncwarp();   // P rows are warp-private

        // O += P V   (keys = 8 k-steps of 8; V [k][n] scalar B-frags)
        uint32_t pb = sb + AP * 4;
        const float* vs = sm + ((kt & 1) ? AV1 : AV0);
#pragma unroll
        for (int ks = 0; ks < 8; ks++) {
            uint32_t pa0[4], pa1[4];
            ldsm4(pa0, a_addr(pb, 68, mrow, ks * 8, lane));
            ldsm4(pa1, a_addr(pb, 68, mrow + 16, ks * 8, lane));
#pragma unroll
            for (int nj = 0; nj < 8; nj++) {
                uint32_t bf[2];
                bf[0] = __float_as_uint(vs[(ks * 8 + tig) * 72 + nj * 8 + g]);
                bf[1] = __float_as_uint(vs[(ks * 8 + tig + 4) * 72 + nj * 8 + g]);
                mma8(o[0][nj], pa0, bf);
                mma8(o[1][nj], pa1, bf);
            }
        }
    }

    // Epilogue: normalize, round, write g_A [b*s][h*64]
    const int b_ = bh >> 3, h = bh & 7;
#pragma unroll
    for (int mt = 0; mt < 2; mt++) {
        float inv0 = 1.f / lr[mt][0], inv1 = 1.f / lr[mt][1];
        int r0 = qt * 128 + mrow + 16 * mt + g;
        float* p0 = g_A + ((size_t)(b_ * SS + r0)) * HID + h * 64;
        float* p1 = p0 + (size_t)8 * HID;
#pragma unroll
        for (int nj = 0; nj < 8; nj++) {
            *(float2*)&p0[nj * 8 + 2 * tig] =
                make_float2(tf32r(o[mt][nj][0] * inv0), tf32r(o[mt][nj][1] * inv0));
            *(float2*)&p1[nj * 8 + 2 * tig] =
                make_float2(tf32r(o[mt][nj][2] * inv1), tf32r(o[mt][nj][3] * inv1));
        }
    }
}

// ===========================================================================
extern "C" void kernel_launch(void* const* d_in, const int* in_sizes, int n_in,
                              void* d_out, int out_size)
{
    const float* X  = (const float*)d_in[0];
    const float* Wq = (const float*)d_in[1];
    const float* bq = (const float*)d_in[2];
    const float* Wk = (const float*)d_in[3];
    const float* bk = (const float*)d_in[4];
    const float* Wv = (const float*)d_in[5];
    const float* bv = (const float*)d_in[6];
    const float* Wo = (const float*)d_in[7];
    const float* bo = (const float*)d_in[8];
    float* out = (float*)d_out;

    cudaFuncSetAttribute(qkv_mma,   cudaFuncAttributeMaxDynamicSharedMemorySize, PROJ_SMEM);
    cudaFuncSetAttribute(oproj_mma, cudaFuncAttributeMaxDynamicSharedMemorySize, PROJ_SMEM);
    cudaFuncSetAttribute(attn_mma,  cudaFuncAttributeMaxDynamicSharedMemorySize, ATTN_SMEM);

    round_pre<<<1184, 256>>>(X, Wq, Wk, Wv, Wo);
    qkv_mma<<<dim3(HID / 128, MM / 128, 3), 128, PROJ_SMEM>>>(bq, bk, bv);
    attn_mma<<<dim3(SS / 128, NB * NH), 128, ATTN_SMEM>>>();
    oproj_mma<<<dim3(VD / 128, MM / 128), 128, PROJ_SMEM>>>(bo, out);
}